// round 2
// baseline (speedup 1.0000x reference)
#include <cuda_runtime.h>
#include <cuda_bf16.h>
#include <stdint.h>

// ---------------- problem constants ----------------
#define BATCH   16384
#define QS      1204
#define FD      7
#define ROWB    (QS*FD*4)          // 33712 bytes per batch row
#define RPC     64                 // rows per CTA
#define NCTA    (BATCH/RPC)        // 256
#define FK      600
#define FKP     640
#define NCH1    20                 // k-chunks of 32 in GEMM1
#define SA      648                // A smem stride (elements) -> conflict-free
#define S2ST    136                // stage-2 A-side stride
#define F1ST    133

// feat streaming chunks
#define CQ      172                // q per chunk (172*7*4 = 4816 B, 16B aligned)
#define CB      4816
#define CPR     7                  // chunks per row
#define TCH     (RPC*CPR)          // 448

// ---------------- smem layout (bytes) ----------------
#define OFF_AH   0
#define OFF_AL   82944             // 64*648*2
#define OFF_R2   165888
// feat phase in R2
#define OFF_RING OFF_R2            // 8*4816 = 38528
#define OFF_SS   (OFF_R2+38528)    // 2*1204*4 = 9632
#define SMEM_TOTAL (OFF_SS+9632)   // 214048
// gemm1 B double buffer in R2
#define OFF_B0H  OFF_R2
#define OFF_B0L  (OFF_R2+8192)
#define OFF_B1H  (OFF_R2+16384)
#define OFF_B1L  (OFF_R2+24576)
// stage3 in R2
#define OFF_WB   OFF_R2            // 128*32*4 = 16384 fp32
#define OFF_F2   (OFF_R2+16384)    // 64*36*4  = 9216
// stage2 in A region
#define OFF_H0H  0
#define OFF_H0L  17408
#define OFF_WH   34816             // 4*4096*2 = 32768
#define OFF_WL   67584
#define OFF_T1H  100352
#define OFF_T1L  117760
#define OFF_F1   34816             // fp32 64*133*4 = 34048, overlays W after gemm3

// ---------------- global scratch: pre-split weights ----------------
__device__ __align__(16) __nv_bfloat16 g_wAh[NCH1*4096];
__device__ __align__(16) __nv_bfloat16 g_wAl[NCH1*4096];
__device__ __align__(16) __nv_bfloat16 g_w1h[4*4096];
__device__ __align__(16) __nv_bfloat16 g_w1l[4*4096];
__device__ __align__(16) __nv_bfloat16 g_w2h[4*4096];
__device__ __align__(16) __nv_bfloat16 g_w2l[4*4096];
__device__ __align__(16) float         g_wBt[128*32];

// ---------------- helpers ----------------
__device__ __forceinline__ void split_bf16(float v, __nv_bfloat16& hi, __nv_bfloat16& lo) {
    hi = __float2bfloat16(v);
    lo = __float2bfloat16(v - __bfloat162float(hi));
}
__device__ __forceinline__ uint32_t pack_bf2(__nv_bfloat16 e0, __nv_bfloat16 e1) {
    return ((uint32_t)__bfloat16_as_ushort(e1) << 16) | (uint32_t)__bfloat16_as_ushort(e0);
}
__device__ __forceinline__ uint32_t smem_u32(const void* p) {
    return (uint32_t)__cvta_generic_to_shared(p);
}
__device__ __forceinline__ void mbar_init(uint32_t mbar, uint32_t cnt) {
    asm volatile("mbarrier.init.shared.b64 [%0], %1;" :: "r"(mbar), "r"(cnt) : "memory");
}
__device__ __forceinline__ void mbar_expect_tx(uint32_t mbar, uint32_t bytes) {
    asm volatile("mbarrier.arrive.expect_tx.shared.b64 _, [%0], %1;" :: "r"(mbar), "r"(bytes) : "memory");
}
__device__ __forceinline__ void mbar_wait(uint32_t mbar, uint32_t parity) {
    asm volatile(
        "{\n\t.reg .pred P;\n"
        "W%=:\n\t"
        "mbarrier.try_wait.parity.acquire.cta.shared::cta.b64 P, [%0], %1, 0x989680;\n\t"
        "@P bra D%=;\n\t"
        "bra W%=;\n"
        "D%=:\n\t}"
        :: "r"(mbar), "r"(parity) : "memory");
}
__device__ __forceinline__ void bulk_in(uint32_t dst, const void* src, uint32_t bytes, uint32_t mbar) {
    asm volatile(
        "cp.async.bulk.shared::cta.global.mbarrier::complete_tx::bytes [%0], [%1], %2, [%3];"
        :: "r"(dst), "l"(src), "r"(bytes), "r"(mbar) : "memory");
}
__device__ __forceinline__ void mma16816(float* c,
    uint32_t a0, uint32_t a1, uint32_t a2, uint32_t a3, uint32_t b0, uint32_t b1)
{
    asm volatile(
        "mma.sync.aligned.m16n8k16.row.col.f32.bf16.bf16.f32 "
        "{%0,%1,%2,%3}, {%4,%5,%6,%7}, {%8,%9}, {%0,%1,%2,%3};\n"
        : "+f"(c[0]), "+f"(c[1]), "+f"(c[2]), "+f"(c[3])
        : "r"(a0), "r"(a1), "r"(a2), "r"(a3), "r"(b0), "r"(b1));
}
// swizzled B read: rows of 64B, byte-in-row rotated by 8*(n&7)
__device__ __forceinline__ uint32_t ldsB(const char* base, int n, int kloc) {
    const int byte = n * 64 + ((2 * kloc + 8 * (n & 7)) & 63);
    return *(const uint32_t*)(base + byte);
}

// ---------------- pre-split kernel ----------------
// wA -> [20][128][32] swizzled hi/lo (k padded to 640); w1/w2 -> [4][128][32]; wB -> transposed fp32
__global__ __launch_bounds__(256) void presplit_kernel(
    const float* __restrict__ wA, const float* __restrict__ w1,
    const float* __restrict__ w2, const float* __restrict__ wB)
{
    int id = blockIdx.x * 256 + threadIdx.x;
    if (id < 81920) {
        const int n = id / FKP, k = id % FKP;
        const float v = (k < FK) ? __ldg(wA + n * FK + k) : 0.f;
        __nv_bfloat16 h, l; split_bf16(v, h, l);
        const int idx = (k >> 5) * 4096 + n * 32 + (((2 * (k & 31) + 8 * (n & 7)) & 63) >> 1);
        g_wAh[idx] = h; g_wAl[idx] = l;
    } else if (id < 98304) {
        const int t = id - 81920, n = t >> 7, k = t & 127;
        __nv_bfloat16 h, l; split_bf16(__ldg(w1 + n * 128 + k), h, l);
        const int idx = (k >> 5) * 4096 + n * 32 + (((2 * (k & 31) + 8 * (n & 7)) & 63) >> 1);
        g_w1h[idx] = h; g_w1l[idx] = l;
    } else if (id < 114688) {
        const int t = id - 98304, n = t >> 7, k = t & 127;
        __nv_bfloat16 h, l; split_bf16(__ldg(w2 + n * 128 + k), h, l);
        const int idx = (k >> 5) * 4096 + n * 32 + (((2 * (k & 31) + 8 * (n & 7)) & 63) >> 1);
        g_w2h[idx] = h; g_w2l[idx] = l;
    } else if (id < 118784) {
        const int t = id - 114688, k = t >> 5, n = t & 31;
        g_wBt[k * 32 + n] = __ldg(wB + n * 128 + k);
    }
}

// ---------------- GEMM inner helpers ----------------
// warp tile 32M x 32N: mt=2, nt=4; g = lane>>2, tg = lane&3
__device__ __forceinline__ void gemm_chunk_A648(
    const __nv_bfloat16* Ah, const __nv_bfloat16* Al,
    const char* Bh, const char* Bl,
    int kbase, float (&acc)[2][4][4], int mb, int nb, int g, int tg)
{
    #pragma unroll
    for (int kk = 0; kk < 2; ++kk) {
        const int kloc = kk * 16 + 2 * tg;
        const int kg = kbase + kloc;
        uint32_t ah[2][4], al[2][4];
        #pragma unroll
        for (int mt = 0; mt < 2; ++mt) {
            const __nv_bfloat16* pa = Ah + (mb + mt * 16 + g) * SA + kg;
            ah[mt][0] = *(const uint32_t*)pa;
            ah[mt][1] = *(const uint32_t*)(pa + 8 * SA);
            ah[mt][2] = *(const uint32_t*)(pa + 8);
            ah[mt][3] = *(const uint32_t*)(pa + 8 * SA + 8);
            const __nv_bfloat16* pl = Al + (mb + mt * 16 + g) * SA + kg;
            al[mt][0] = *(const uint32_t*)pl;
            al[mt][1] = *(const uint32_t*)(pl + 8 * SA);
            al[mt][2] = *(const uint32_t*)(pl + 8);
            al[mt][3] = *(const uint32_t*)(pl + 8 * SA + 8);
        }
        #pragma unroll
        for (int nt = 0; nt < 4; ++nt) {
            const int n = nb + nt * 8 + g;
            const uint32_t bh0 = ldsB(Bh, n, kloc), bh1 = ldsB(Bh, n, kloc + 8);
            const uint32_t bl0 = ldsB(Bl, n, kloc), bl1 = ldsB(Bl, n, kloc + 8);
            #pragma unroll
            for (int mt = 0; mt < 2; ++mt) {
                mma16816(acc[mt][nt], ah[mt][0], ah[mt][1], ah[mt][2], ah[mt][3], bh0, bh1);
                mma16816(acc[mt][nt], ah[mt][0], ah[mt][1], ah[mt][2], ah[mt][3], bl0, bl1);
                mma16816(acc[mt][nt], al[mt][0], al[mt][1], al[mt][2], al[mt][3], bh0, bh1);
            }
        }
    }
}

// A-side stride 136 (H0/T1), B = chunked [4][128][32] swizzled, K = 128
__device__ __forceinline__ void gemm_128(
    const __nv_bfloat16* Ah, const __nv_bfloat16* Al,
    const char* Bh, const char* Bl,
    float (&acc)[2][4][4], int mb, int nb, int g, int tg)
{
    #pragma unroll
    for (int kk = 0; kk < 8; ++kk) {
        const int k0 = kk * 16 + 2 * tg;
        const int ch = k0 >> 5, kloc = k0 & 31;
        const char* BhC = Bh + ch * 8192;
        const char* BlC = Bl + ch * 8192;
        uint32_t ah[2][4], al[2][4];
        #pragma unroll
        for (int mt = 0; mt < 2; ++mt) {
            const __nv_bfloat16* pa = Ah + (mb + mt * 16 + g) * S2ST + k0;
            ah[mt][0] = *(const uint32_t*)pa;
            ah[mt][1] = *(const uint32_t*)(pa + 8 * S2ST);
            ah[mt][2] = *(const uint32_t*)(pa + 8);
            ah[mt][3] = *(const uint32_t*)(pa + 8 * S2ST + 8);
            const __nv_bfloat16* pl = Al + (mb + mt * 16 + g) * S2ST + k0;
            al[mt][0] = *(const uint32_t*)pl;
            al[mt][1] = *(const uint32_t*)(pl + 8 * S2ST);
            al[mt][2] = *(const uint32_t*)(pl + 8);
            al[mt][3] = *(const uint32_t*)(pl + 8 * S2ST + 8);
        }
        #pragma unroll
        for (int nt = 0; nt < 4; ++nt) {
            const int n = nb + nt * 8 + g;
            const uint32_t bh0 = ldsB(BhC, n, kloc), bh1 = ldsB(BhC, n, kloc + 8);
            const uint32_t bl0 = ldsB(BlC, n, kloc), bl1 = ldsB(BlC, n, kloc + 8);
            #pragma unroll
            for (int mt = 0; mt < 2; ++mt) {
                mma16816(acc[mt][nt], ah[mt][0], ah[mt][1], ah[mt][2], ah[mt][3], bh0, bh1);
                mma16816(acc[mt][nt], ah[mt][0], ah[mt][1], ah[mt][2], ah[mt][3], bl0, bl1);
                mma16816(acc[mt][nt], al[mt][0], al[mt][1], al[mt][2], al[mt][3], bh0, bh1);
            }
        }
    }
}

__device__ __forceinline__ void zero_acc(float (&acc)[2][4][4]) {
    #pragma unroll
    for (int a = 0; a < 2; ++a)
        #pragma unroll
        for (int b = 0; b < 4; ++b)
            #pragma unroll
            for (int c = 0; c < 4; ++c) acc[a][b][c] = 0.f;
}

__device__ __forceinline__ void store_split_pair(
    __nv_bfloat16* H, __nv_bfloat16* L, int m, int col, float v0, float v1)
{
    __nv_bfloat16 h0, l0, h1, l1;
    split_bf16(v0, h0, l0);
    split_bf16(v1, h1, l1);
    *(uint32_t*)(H + m * S2ST + col) = pack_bf2(h0, h1);
    *(uint32_t*)(L + m * S2ST + col) = pack_bf2(l0, l1);
}

// ---------------- fused kernel ----------------
__global__ __launch_bounds__(256, 1) void fused_kernel(
    const float* __restrict__ x,
    const float* __restrict__ w_step, const float* __restrict__ b_step,
    const float* __restrict__ bA,
    const float* __restrict__ b1, const float* __restrict__ b2,
    const float* __restrict__ bB,
    const float* __restrict__ wC, const float* __restrict__ bC,
    float* __restrict__ out)
{
    extern __shared__ __align__(16) char smem[];
    __shared__ __align__(8) unsigned long long mb_x[8];
    __shared__ __align__(8) unsigned long long mb_b[2];

    const int tid  = threadIdx.x;
    const int wid  = tid >> 5;
    const int lane = tid & 31;
    const int g    = lane >> 2;
    const int tg   = lane & 3;
    const int mb   = (wid & 1) * 32;
    const int nb   = (wid >> 1) * 32;
    const int row0 = blockIdx.x * RPC;

    __nv_bfloat16* Ah = (__nv_bfloat16*)(smem + OFF_AH);
    __nv_bfloat16* Al = (__nv_bfloat16*)(smem + OFF_AL);
    float* ss = (float*)(smem + OFF_SS);

    // init mbarriers + zero A k-padding
    if (tid == 0) {
        #pragma unroll
        for (int i = 0; i < 8; ++i) mbar_init(smem_u32(&mb_x[i]), 1);
        mbar_init(smem_u32(&mb_b[0]), 1);
        mbar_init(smem_u32(&mb_b[1]), 1);
    }
    for (int i = tid; i < RPC * (FKP - FK); i += 256) {
        const int r = i / (FKP - FK), j = FK + i % (FKP - FK);
        Ah[r * SA + j] = __float2bfloat16(0.f);
        Al[r * SA + j] = __float2bfloat16(0.f);
    }
    __syncthreads();

    // ---------- feat phase: TMA ring over x ----------
    const char* xbase = (const char*)x + (size_t)blockIdx.x * (RPC * (size_t)ROWB);
    const uint32_t ringu = smem_u32(smem + OFF_RING);
    if (tid == 0) {
        #pragma unroll
        for (int i = 0; i < 8; ++i) {
            const uint32_t m = smem_u32(&mb_x[i]);
            mbar_expect_tx(m, CB);
            bulk_in(ringu + i * CB, xbase + (size_t)i * CB, CB, m);
        }
    }
    const float w0 = __ldg(w_step + 0), w1c = __ldg(w_step + 1), w2c = __ldg(w_step + 2),
                w3 = __ldg(w_step + 3), w4 = __ldg(w_step + 4), w5 = __ldg(w_step + 5),
                w6 = __ldg(w_step + 6), bsv = __ldg(b_step);

    int gc = 0;
    for (int it = 0; it < TCH / 2; ++it, gc += 2) {
        int rEnd = -1;
        #pragma unroll
        for (int k2 = 0; k2 < 2; ++k2) {
            const int cc = gc + k2, s = cc & 7, ph = (cc >> 3) & 1;
            mbar_wait(smem_u32(&mb_x[s]), ph);
            const int r = cc / 7, cq = cc - r * 7;
            if (cc % 7 == 6) rEnd = r;
            if (tid < CQ) {
                const float* p = (const float*)(smem + OFF_RING + s * CB) + tid * 7;
                float v = fmaf(p[0], w0, fmaf(p[1], w1c, fmaf(p[2], w2c,
                          fmaf(p[3], w3, fmaf(p[4], w4, fmaf(p[5], w5, p[6] * w6))))));
                ss[(r & 1) * QS + cq * CQ + tid] = v + bsv;
            }
        }
        __syncthreads();
        if (tid == 0) {
            #pragma unroll
            for (int k2 = 0; k2 < 2; ++k2) {
                const int nc = gc + 8 + k2;
                if (nc < TCH) {
                    const int s = nc & 7;
                    const uint32_t m = smem_u32(&mb_x[s]);
                    mbar_expect_tx(m, CB);
                    bulk_in(ringu + s * CB, xbase + (size_t)nc * CB, CB, m);
                }
            }
        }
        if (rEnd >= 0) {
            const float* sr = ss + (rEnd & 1) * QS;
            for (int j = tid; j < FK; j += 256) {
                const int bl = j / 5, off = j % 5;
                const float* p = sr + off + bl * 10;
                float m = p[0];
                #pragma unroll
                for (int i = 1; i < 10; ++i) m = fmaxf(m, p[i]);
                __nv_bfloat16 h, l; split_bf16(m, h, l);
                Ah[rEnd * SA + j] = h;
                Al[rEnd * SA + j] = l;
            }
        }
    }
    __syncthreads();

    // ---------- GEMM1: h0 = relu(feat @ wA^T + bA) ----------
    float acc[2][4][4];
    zero_acc(acc);
    {
        const uint32_t b0h = smem_u32(smem + OFF_B0H);
        if (tid == 0) {
            #pragma unroll
            for (int c = 0; c < 2; ++c) {
                const uint32_t m = smem_u32(&mb_b[c]);
                mbar_expect_tx(m, 16384);
                bulk_in(b0h + c * 16384,        (const char*)g_wAh + c * 8192, 8192, m);
                bulk_in(b0h + c * 16384 + 8192, (const char*)g_wAl + c * 8192, 8192, m);
            }
        }
        for (int c = 0; c < NCH1; ++c) {
            const int buf = c & 1;
            mbar_wait(smem_u32(&mb_b[buf]), (c >> 1) & 1);
            gemm_chunk_A648(Ah, Al,
                            smem + OFF_B0H + buf * 16384,
                            smem + OFF_B0H + buf * 16384 + 8192,
                            c * 32, acc, mb, nb, g, tg);
            __syncthreads();
            if (tid == 0 && c + 2 < NCH1) {
                const int nc = c + 2;
                const uint32_t m = smem_u32(&mb_b[buf]);
                mbar_expect_tx(m, 16384);
                bulk_in(b0h + buf * 16384,        (const char*)g_wAh + nc * 8192, 8192, m);
                bulk_in(b0h + buf * 16384 + 8192, (const char*)g_wAl + nc * 8192, 8192, m);
            }
        }
    }

    // epilogue 1: h0 -> split bf16 H0 (A region now dead)
    __nv_bfloat16* H0h = (__nv_bfloat16*)(smem + OFF_H0H);
    __nv_bfloat16* H0l = (__nv_bfloat16*)(smem + OFF_H0L);
    #pragma unroll
    for (int mt = 0; mt < 2; ++mt) {
        const int m0 = mb + mt * 16 + g;
        #pragma unroll
        for (int nt = 0; nt < 4; ++nt) {
            const int col = nb + nt * 8 + 2 * tg;
            const float bb0 = __ldg(bA + col), bb1 = __ldg(bA + col + 1);
            store_split_pair(H0h, H0l, m0,     col,
                             fmaxf(acc[mt][nt][0] + bb0, 0.f),
                             fmaxf(acc[mt][nt][1] + bb1, 0.f));
            store_split_pair(H0h, H0l, m0 + 8, col,
                             fmaxf(acc[mt][nt][2] + bb0, 0.f),
                             fmaxf(acc[mt][nt][3] + bb1, 0.f));
        }
    }
    // copy w1 hi/lo + wB (plain, L2-resident)
    {
        uint4* dh = (uint4*)(smem + OFF_WH);
        uint4* dl = (uint4*)(smem + OFF_WL);
        const uint4* sh = (const uint4*)g_w1h;
        const uint4* sl = (const uint4*)g_w1l;
        #pragma unroll 4
        for (int i = tid; i < 2048; i += 256) { dh[i] = sh[i]; dl[i] = sl[i]; }
        float4* wb = (float4*)(smem + OFF_WB);
        const float4* ws = (const float4*)g_wBt;
        #pragma unroll 2
        for (int i = tid; i < 1024; i += 256) wb[i] = ws[i];
    }
    __syncthreads();

    // ---------- GEMM2: t1 = relu(h0 @ w1^T + b1) ----------
    zero_acc(acc);
    gemm_128(H0h, H0l, smem + OFF_WH, smem + OFF_WL, acc, mb, nb, g, tg);
    {
        __nv_bfloat16* T1h = (__nv_bfloat16*)(smem + OFF_T1H);
        __nv_bfloat16* T1l = (__nv_bfloat16*)(smem + OFF_T1L);
        #pragma unroll
        for (int mt = 0; mt < 2; ++mt) {
            const int m0 = mb + mt * 16 + g;
            #pragma unroll
            for (int nt = 0; nt < 4; ++nt) {
                const int col = nb + nt * 8 + 2 * tg;
                const float bb0 = __ldg(b1 + col), bb1 = __ldg(b1 + col + 1);
                store_split_pair(T1h, T1l, m0,     col,
                                 fmaxf(acc[mt][nt][0] + bb0, 0.f),
                                 fmaxf(acc[mt][nt][1] + bb1, 0.f));
                store_split_pair(T1h, T1l, m0 + 8, col,
                                 fmaxf(acc[mt][nt][2] + bb0, 0.f),
                                 fmaxf(acc[mt][nt][3] + bb1, 0.f));
            }
        }
    }
    __syncthreads();
    // copy w2 hi/lo over w1
    {
        uint4* dh = (uint4*)(smem + OFF_WH);
        uint4* dl = (uint4*)(smem + OFF_WL);
        const uint4* sh = (const uint4*)g_w2h;
        const uint4* sl = (const uint4*)g_w2l;
        #pragma unroll 4
        for (int i = tid; i < 2048; i += 256) { dh[i] = sh[i]; dl[i] = sl[i]; }
    }
    __syncthreads();

    // ---------- GEMM3: h1 = relu(h0 + t1 @ w2^T + b2) -> fp32 F1 ----------
    zero_acc(acc);
    gemm_128((__nv_bfloat16*)(smem + OFF_T1H), (__nv_bfloat16*)(smem + OFF_T1L),
             smem + OFF_WH, smem + OFF_WL, acc, mb, nb, g, tg);
    __syncthreads();   // all W reads done before F1 overlays W
    {
        float* F1 = (float*)(smem + OFF_F1);
        #pragma unroll
        for (int mt = 0; mt < 2; ++mt) {
            const int m0 = mb + mt * 16 + g;
            #pragma unroll
            for (int nt = 0; nt < 4; ++nt) {
                const int col = nb + nt * 8 + 2 * tg;
                const float bb0 = __ldg(b2 + col), bb1 = __ldg(b2 + col + 1);
                const float h00 = __bfloat162float(H0h[m0 * S2ST + col])
                                + __bfloat162float(H0l[m0 * S2ST + col]);
                const float h01 = __bfloat162float(H0h[m0 * S2ST + col + 1])
                                + __bfloat162float(H0l[m0 * S2ST + col + 1]);
                const float h10 = __bfloat162float(H0h[(m0 + 8) * S2ST + col])
                                + __bfloat162float(H0l[(m0 + 8) * S2ST + col]);
                const float h11 = __bfloat162float(H0h[(m0 + 8) * S2ST + col + 1])
                                + __bfloat162float(H0l[(m0 + 8) * S2ST + col + 1]);
                F1[m0 * F1ST + col]           = fmaxf(h00 + acc[mt][nt][0] + bb0, 0.f);
                F1[m0 * F1ST + col + 1]       = fmaxf(h01 + acc[mt][nt][1] + bb1, 0.f);
                F1[(m0 + 8) * F1ST + col]     = fmaxf(h10 + acc[mt][nt][2] + bb0, 0.f);
                F1[(m0 + 8) * F1ST + col + 1] = fmaxf(h11 + acc[mt][nt][3] + bb1, 0.f);
            }
        }
    }
    __syncthreads();

    // ---------- Stage 3: h2 = relu(h1 @ wB^T + bB) ----------
    {
        const float* F1 = (const float*)(smem + OFF_F1);
        const float* wBs = (const float*)(smem + OFF_WB);
        float* F2 = (float*)(smem + OFF_F2);
        const int r  = tid >> 2;
        const int n0 = (tid & 3) * 8;
        float a3[8];
        #pragma unroll
        for (int i = 0; i < 8; ++i) a3[i] = 0.f;
        #pragma unroll 4
        for (int k = 0; k < 128; ++k) {
            const float hv = F1[r * F1ST + k];
            const float4 q0 = *(const float4*)(wBs + k * 32 + n0);
            const float4 q1 = *(const float4*)(wBs + k * 32 + n0 + 4);
            a3[0] = fmaf(hv, q0.x, a3[0]); a3[1] = fmaf(hv, q0.y, a3[1]);
            a3[2] = fmaf(hv, q0.z, a3[2]); a3[3] = fmaf(hv, q0.w, a3[3]);
            a3[4] = fmaf(hv, q1.x, a3[4]); a3[5] = fmaf(hv, q1.y, a3[5]);
            a3[6] = fmaf(hv, q1.z, a3[6]); a3[7] = fmaf(hv, q1.w, a3[7]);
        }
        #pragma unroll
        for (int n = 0; n < 8; ++n)
            F2[r * 36 + n0 + n] = fmaxf(a3[n] + __ldg(bB + n0 + n), 0.f);
    }
    __syncthreads();

    // ---------- Stage 4: logits ----------
    if (tid < 128) {
        const float* F2 = (const float*)(smem + OFF_F2);
        const int r = tid >> 1, c = tid & 1;
        float s = __ldg(bC + c);
        #pragma unroll
        for (int k = 0; k < 32; ++k)
            s = fmaf(F2[r * 36 + k], __ldg(wC + c * 32 + k), s);
        out[(size_t)(row0 + r) * 2 + c] = s;
    }
}

// ---------------- launch ----------------
extern "C" void kernel_launch(void* const* d_in, const int* in_sizes, int n_in,
                              void* d_out, int out_size)
{
    const float* x      = (const float*)d_in[0];
    const float* w_step = (const float*)d_in[1];
    const float* b_step = (const float*)d_in[2];
    const float* wA     = (const float*)d_in[3];
    const float* bA     = (const float*)d_in[4];
    const float* w1     = (const float*)d_in[5];
    const float* b1     = (const float*)d_in[6];
    const float* w2     = (const float*)d_in[7];
    const float* b2     = (const float*)d_in[8];
    const float* wB     = (const float*)d_in[9];
    const float* bB     = (const float*)d_in[10];
    const float* wC     = (const float*)d_in[11];
    const float* bC     = (const float*)d_in[12];
    float* out          = (float*)d_out;

    cudaFuncSetAttribute(fused_kernel, cudaFuncAttributeMaxDynamicSharedMemorySize, SMEM_TOTAL);

    presplit_kernel<<<464, 256>>>(wA, w1, w2, wB);
    fused_kernel<<<NCTA, 256, SMEM_TOTAL>>>(x, w_step, b_step, bA, b1, b2, bB, wC, bC, out);
}